// round 4
// baseline (speedup 1.0000x reference)
#include <cuda_runtime.h>
#include <cstdint>

#define M_DIM   64
#define K_DIM   4096
#define N_DIM   11008
#define GROUP   128
#define NGROUPS 32
#define NTILE   64
#define KC      64
#define NTHREADS 128

typedef unsigned long long ull;

// x transposed to [K][M] so GEMM staging is coalesced + conflict-free.
// __device__ global scratch (allocation-free per harness rules). 1 MB.
__device__ float g_xT[K_DIM * M_DIM];

// ---------------------------------------------------------------------------
// Kernel 1: tiled transpose x[M,K] -> g_xT[K,M]
// ---------------------------------------------------------------------------
__global__ void transpose_x_kernel(const float* __restrict__ x) {
    __shared__ float t[32][33];
    const int kb = blockIdx.x * 32;
    const int mb = blockIdx.y * 32;
    const int tx = threadIdx.x;   // 0..31
    const int ty = threadIdx.y;   // 0..7
#pragma unroll
    for (int j = 0; j < 32; j += 8)
        t[ty + j][tx] = x[(mb + ty + j) * K_DIM + (kb + tx)];
    __syncthreads();
#pragma unroll
    for (int j = 0; j < 32; j += 8)
        g_xT[(kb + ty + j) * M_DIM + (mb + tx)] = t[tx][ty + j];
}

// ---------------------------------------------------------------------------
// Kernel 2: fused int4-dequant GEMM, fp32 accum via packed fma.rn.f32x2
//   out[m,n] = sum_k x[m,k] * s[g(k),n]*(q[k,n] - z[g(k),n]) + bias[n]
// CTA tile: 64(M) x 64(N), 128 threads, micro-tile 8m x 4n (m packed in f32x2)
// ---------------------------------------------------------------------------
union F4U {
    float4 f4;
    float  f[4];
    ull    u2[2];
};
union U2F {
    ull    u;
    float2 f2;
};

__global__ __launch_bounds__(NTHREADS)
void gptq_gemm_kernel(const int*   __restrict__ qweight,  // [K/8, N]
                      const int*   __restrict__ qzeros,   // [NGROUPS, N/8]
                      const float* __restrict__ scales,   // [NGROUPS, N]
                      const float* __restrict__ bias,     // [N]
                      float*       __restrict__ out)      // [M, N]
{
    __shared__ float x_s[KC * M_DIM];   // [k][m]  16 KB
    __shared__ float w_s[KC * NTILE];   // [k][n]  16 KB

    const int tid = threadIdx.x;
    const int n0  = blockIdx.x * NTILE;

    // GEMM micro-tile coordinates
    const int tx = tid & 15;            // n-quad index (16 quads = 64 cols)
    const int ty = tid >> 4;            // m-octet index (8 octets = 64 rows)
    const int m0 = ty * 8;
    const int nn = n0 + tx * 4;

    // Dequant assignment: fixed column per thread, 2 halves of kw rows
    const int ncol = tid & 63;          // local n for dequant
    const int kwh  = tid >> 6;          // 0 or 1
    const int gn   = n0 + ncol;         // global n for dequant

    ull acc[4][4];
#pragma unroll
    for (int p = 0; p < 4; p++)
#pragma unroll
        for (int j = 0; j < 4; j++) acc[p][j] = 0ull;

    for (int g = 0; g < NGROUPS; g++) {
        // Per-group, per-column constants (exact dequant):
        //   q - z = as_float(0x4B000000 | nib) - (8388608 + z)   (all exact)
        //   W     = s * (q - z)
        const float s  = scales[g * N_DIM + gn];
        const int   zw = qzeros[g * (N_DIM / 8) + (gn >> 3)];
        const int   z  = ((zw >> ((gn & 7) * 4)) & 15) + 1;
        const float cz = 8388608.0f + (float)z;

#pragma unroll 1
        for (int half = 0; half < 2; half++) {
            const int kc = g * GROUP + half * KC;
            __syncthreads();

            // ---- stage x: contiguous copy from g_xT (coalesced, no conflicts)
            {
                const float4* src = reinterpret_cast<const float4*>(g_xT + kc * M_DIM);
                float4*       dst = reinterpret_cast<float4*>(x_s);
#pragma unroll
                for (int i = 0; i < (KC * M_DIM / 4) / NTHREADS; i++)   // 8 iters
                    dst[i * NTHREADS + tid] = src[i * NTHREADS + tid];
            }

            // ---- stage w: dequant int4 -> fp32 into SMEM (exact)
            {
                const int kwbase = kc >> 3;   // row index into qweight
#pragma unroll
                for (int it = 0; it < 4; it++) {
                    const int kw = it * 2 + kwh;                 // 0..7
                    const unsigned int word =
                        (unsigned int)qweight[(kwbase + kw) * N_DIM + gn];
#pragma unroll
                    for (int jj = 0; jj < 8; jj++) {
                        const unsigned int nib = (word >> (jj * 4)) & 15u;
                        const float f = __uint_as_float(0x4B000000u | nib) - cz; // = q - z exact
                        w_s[(kw * 8 + jj) * NTILE + ncol] = s * f;
                    }
                }
            }
            __syncthreads();

            // ---- mainloop: 16 packed FMAs (32 fp32 FMAs) per k per thread
#pragma unroll 8
            for (int k = 0; k < KC; k++) {
                F4U xa, xb, wv;
                xa.f4 = *reinterpret_cast<const float4*>(&x_s[k * M_DIM + m0]);
                xb.f4 = *reinterpret_cast<const float4*>(&x_s[k * M_DIM + m0 + 4]);
                wv.f4 = *reinterpret_cast<const float4*>(&w_s[k * NTILE + tx * 4]);

                ull w2[4];
#pragma unroll
                for (int j = 0; j < 4; j++)
                    asm("mov.b64 %0, {%1, %1};" : "=l"(w2[j]) : "f"(wv.f[j]));

                const ull xp[4] = { xa.u2[0], xa.u2[1], xb.u2[0], xb.u2[1] };
#pragma unroll
                for (int p = 0; p < 4; p++)
#pragma unroll
                    for (int j = 0; j < 4; j++)
                        asm("fma.rn.f32x2 %0, %1, %2, %0;"
                            : "+l"(acc[p][j]) : "l"(xp[p]), "l"(w2[j]));
            }
        }
    }

    // ---- epilogue: unpack pairs, add bias, store float4 rows
    const float4 b4 = *reinterpret_cast<const float4*>(&bias[nn]);
#pragma unroll
    for (int p = 0; p < 4; p++) {
        float lo[4], hi[4];
#pragma unroll
        for (int j = 0; j < 4; j++) {
            U2F u; u.u = acc[p][j];
            lo[j] = u.f2.x;   // row m0 + 2p
            hi[j] = u.f2.y;   // row m0 + 2p + 1
        }
        float* row0 = out + (size_t)(m0 + 2 * p) * N_DIM + nn;
        float* row1 = row0 + N_DIM;
        float4 v0 = make_float4(lo[0] + b4.x, lo[1] + b4.y, lo[2] + b4.z, lo[3] + b4.w);
        float4 v1 = make_float4(hi[0] + b4.x, hi[1] + b4.y, hi[2] + b4.z, hi[3] + b4.w);
        *reinterpret_cast<float4*>(row0) = v0;
        *reinterpret_cast<float4*>(row1) = v1;
    }
}

// ---------------------------------------------------------------------------
// Launch (graph-capturable: two kernel launches on the default stream)
// ---------------------------------------------------------------------------
extern "C" void kernel_launch(void* const* d_in, const int* in_sizes, int n_in,
                              void* d_out, int out_size) {
    const float* x       = (const float*)d_in[0];
    const int*   qweight = (const int*)  d_in[1];
    const int*   qzeros  = (const int*)  d_in[2];
    const float* scales  = (const float*)d_in[3];
    const float* bias    = (const float*)d_in[4];
    float*       out     = (float*)d_out;

    transpose_x_kernel<<<dim3(K_DIM / 32, M_DIM / 32), dim3(32, 8)>>>(x);
    gptq_gemm_kernel<<<N_DIM / NTILE, NTHREADS>>>(qweight, qzeros, scales, bias, out);
}

// round 7
// speedup vs baseline: 3.9620x; 3.9620x over previous
#include <cuda_runtime.h>
#include <cuda_fp16.h>
#include <cstdint>

#define M_DIM    64
#define K_DIM    4096
#define N_DIM    11008
#define NGROUPS  32
#define KC       64                    // k per chunk
#define NCHUNKS  (K_DIM / KC)          // 64
#define NTILE    32                    // n columns per CTA
#define NTHREADS 256

// One-time fp16 image of x with k-permutation baked in:
// within each 8-k word, slot p holds original nibble index jmap[p],
// jmap = {0,4,1,5,2,6,3,7}  (matches the LOP3 pair extraction (j, j+4)).
__device__ __half g_xh[M_DIM * K_DIM];   // 512 KB

__device__ __forceinline__ uint32_t smem_u32(const void* p) {
    uint32_t a;
    asm("{ .reg .u64 t; cvta.to.shared.u64 t, %1; cvt.u32.u64 %0, t; }" : "=r"(a) : "l"(p));
    return a;
}

// ---------------------------------------------------------------------------
// Kernel 1: x[M,K] fp32 -> g_xh fp16 with permuted k-order within 8-k words
// ---------------------------------------------------------------------------
__global__ __launch_bounds__(256) void prep_x_kernel(const float* __restrict__ x) {
    const int t = blockIdx.x * 256 + threadIdx.x;   // 32768 threads
    const int i = t & 511;                          // k-word (8 k each)
    const int m = t >> 9;                           // 0..63
    const float* src = x + m * K_DIM + 8 * i;
    __half2 h[4];
    h[0] = __floats2half2_rn(src[0], src[4]);
    h[1] = __floats2half2_rn(src[1], src[5]);
    h[2] = __floats2half2_rn(src[2], src[6]);
    h[3] = __floats2half2_rn(src[3], src[7]);
    *reinterpret_cast<uint4*>(g_xh + m * K_DIM + 8 * i) = *reinterpret_cast<const uint4*>(h);
}

// ---------------------------------------------------------------------------
// Kernel 2: fused int4-dequant GEMM via mma.sync m16n8k16 (fp16 in, fp32 acc)
// CTA: 64m x 32n, 8 warps (4m x 2n), warp tile 16m x 16n, K chunked at 64.
// SMEM swizzle: 16B group kg at row r lives at  r*128 + ((kg ^ (r&7))*16).
// ---------------------------------------------------------------------------
__global__ __launch_bounds__(NTHREADS, 2)
void gptq_hmma_kernel(const int*   __restrict__ qweight,  // [K/8, N]
                      const int*   __restrict__ qzeros,   // [NGROUPS, N/8]
                      const float* __restrict__ scales,   // [NGROUPS, N]
                      const float* __restrict__ bias,     // [N]
                      float*       __restrict__ out)      // [M, N]
{
    __shared__ __half a_s[2][M_DIM * KC];   // x tile   2 x 8 KB
    __shared__ __half w_s[2][NTILE * KC];   // W tile   2 x 4 KB

    const int tid  = threadIdx.x;
    const int lane = tid & 31;
    const int wid  = tid >> 5;
    const int nblk = blockIdx.x * NTILE;

    const uint32_t a_base = smem_u32(a_s);
    const uint32_t w_base = smem_u32(w_s);

    // ---- dequant assignment: one qweight word / thread / chunk
    const int dq_n  = tid & 31;             // local n
    const int dq_kw = tid >> 5;             // word-in-chunk 0..7
    const int dq_gn = nblk + dq_n;
    const uint32_t dq_sts = w_base + (uint32_t)(dq_n * 128 + ((dq_kw ^ (dq_n & 7)) * 16));

    // ---- x stage assignment: two 16B groups / thread / chunk
    // group v: m = v>>3, kg = v&7
    const int xm0 = tid >> 3, xkg0 = tid & 7;
    const int xm1 = (tid + 256) >> 3, xkg1 = tid & 7;
    const uint32_t xs_dst0 = a_base + (uint32_t)(xm0 * 128 + ((xkg0 ^ (xm0 & 7)) * 16));
    const uint32_t xs_dst1 = a_base + (uint32_t)(xm1 * 128 + ((xkg1 ^ (xm1 & 7)) * 16));

    // ---- compute assignment
    const int wm = wid & 3, wn = wid >> 2;
    const int m0  = wm * 16;
    const int nw0 = wn * 16;
    const int lrow_a = m0  + (lane & 15);
    const int lrow_b = nw0 + (lane & 15);
    const int khalf  = lane >> 4;           // 0: k+0, 1: k+8
    const uint32_t ldm_a = a_base + (uint32_t)(lrow_a * 128);
    const uint32_t ldm_b = w_base + (uint32_t)(lrow_b * 128);
    const int swz_a = lrow_a & 7, swz_b = lrow_b & 7;

    float acc[2][4] = {};

    // ================= stage chunk 0 =================
    {
        const __half* src0 = g_xh + xm0 * K_DIM + xkg0 * 8;
        const __half* src1 = g_xh + xm1 * K_DIM + xkg1 * 8;
        asm volatile("cp.async.cg.shared.global [%0], [%1], 16;" :: "r"(xs_dst0), "l"(src0) : "memory");
        asm volatile("cp.async.cg.shared.global [%0], [%1], 16;" :: "r"(xs_dst1), "l"(src1) : "memory");
        asm volatile("cp.async.commit_group;" ::: "memory");

        const unsigned word = (unsigned)qweight[dq_kw * N_DIM + dq_gn];
        const float    s    = scales[dq_gn];
        const int      zw   = qzeros[dq_gn >> 3];
        const int      z    = ((zw >> ((dq_gn & 7) * 4)) & 15) + 1;
        const uint32_t zz   = 0x64006400u + (uint32_t)z * 0x00010001u;
        const uint16_t hb   = __half_as_ushort(__float2half_rn(s));
        const uint32_t s2   = ((uint32_t)hb << 16) | hb;
        uint32_t r[4];
#pragma unroll
        for (int j = 0; j < 4; j++) {
            uint32_t p;
            asm("lop3.b32 %0, %1, 0x000F000F, 0x64006400, 0xEA;" : "=r"(p) : "r"(word >> (4 * j)));
            asm("sub.rn.f16x2 %0, %0, %1;" : "+r"(p) : "r"(zz));
            asm("mul.rn.f16x2 %0, %1, %2;" : "=r"(r[j]) : "r"(p), "r"(s2));
        }
        asm volatile("st.shared.v4.b32 [%0], {%1,%2,%3,%4};"
            :: "r"(dq_sts), "r"(r[0]), "r"(r[1]), "r"(r[2]), "r"(r[3]) : "memory");
        asm volatile("cp.async.wait_group 0;" ::: "memory");
    }
    __syncthreads();

    // ================= main loop =================
#pragma unroll 1
    for (int c = 0; c < NCHUNKS; c++) {
        const uint32_t abuf = a_base; (void)abuf;
        const uint32_t aoff = (uint32_t)((c & 1) * (M_DIM * KC * 2));
        const uint32_t woff = (uint32_t)((c & 1) * (NTILE * KC * 2));
        const uint32_t naoff = (uint32_t)(((c + 1) & 1) * (M_DIM * KC * 2));
        const uint32_t nwoff = (uint32_t)(((c + 1) & 1) * (NTILE * KC * 2));

        unsigned nword = 0; uint32_t nzz = 0, ns2 = 0;
        const bool has_next = (c + 1 < NCHUNKS);
        if (has_next) {
            const int nc = c + 1;
            // x prefetch (async)
            const __half* src0 = g_xh + xm0 * K_DIM + nc * KC + xkg0 * 8;
            const __half* src1 = g_xh + xm1 * K_DIM + nc * KC + xkg1 * 8;
            asm volatile("cp.async.cg.shared.global [%0], [%1], 16;" :: "r"(xs_dst0 + naoff), "l"(src0) : "memory");
            asm volatile("cp.async.cg.shared.global [%0], [%1], 16;" :: "r"(xs_dst1 + naoff), "l"(src1) : "memory");
            asm volatile("cp.async.commit_group;" ::: "memory");
            // W inputs (LDG overlaps the MMA block below)
            const int g = nc >> 1;
            nword = (unsigned)qweight[(nc * 8 + dq_kw) * N_DIM + dq_gn];
            const float s  = scales[g * N_DIM + dq_gn];
            const int   zw = qzeros[g * (N_DIM / 8) + (dq_gn >> 3)];
            const int   z  = ((zw >> ((dq_gn & 7) * 4)) & 15) + 1;
            nzz = 0x64006400u + (uint32_t)z * 0x00010001u;
            const uint16_t hb = __half_as_ushort(__float2half_rn(s));
            ns2 = ((uint32_t)hb << 16) | hb;
        }

        // ---- compute chunk c: 4 k-tiles of 16
#pragma unroll
        for (int kt = 0; kt < 4; kt++) {
            const int kg = 2 * kt + khalf;
            uint32_t a0, a1, a2, a3, b0, b1, b2, b3;
            asm volatile("ldmatrix.sync.aligned.m8n8.x4.shared.b16 {%0,%1,%2,%3}, [%4];"
                : "=r"(a0), "=r"(a1), "=r"(a2), "=r"(a3)
                : "r"(ldm_a + aoff + (uint32_t)((kg ^ swz_a) * 16)));
            asm volatile("ldmatrix.sync.aligned.m8n8.x4.shared.b16 {%0,%1,%2,%3}, [%4];"
                : "=r"(b0), "=r"(b1), "=r"(b2), "=r"(b3)
                : "r"(ldm_b + woff + (uint32_t)((kg ^ swz_b) * 16)));
            asm volatile(
                "mma.sync.aligned.m16n8k16.row.col.f32.f16.f16.f32 "
                "{%0,%1,%2,%3}, {%4,%5,%6,%7}, {%8,%9}, {%0,%1,%2,%3};"
                : "+f"(acc[0][0]), "+f"(acc[0][1]), "+f"(acc[0][2]), "+f"(acc[0][3])
                : "r"(a0), "r"(a1), "r"(a2), "r"(a3), "r"(b0), "r"(b2));
            asm volatile(
                "mma.sync.aligned.m16n8k16.row.col.f32.f16.f16.f32 "
                "{%0,%1,%2,%3}, {%4,%5,%6,%7}, {%8,%9}, {%0,%1,%2,%3};"
                : "+f"(acc[1][0]), "+f"(acc[1][1]), "+f"(acc[1][2]), "+f"(acc[1][3])
                : "r"(a0), "r"(a1), "r"(a2), "r"(a3), "r"(b1), "r"(b3));
        }

        if (has_next) {
            uint32_t r[4];
#pragma unroll
            for (int j = 0; j < 4; j++) {
                uint32_t p;
                asm("lop3.b32 %0, %1, 0x000F000F, 0x64006400, 0xEA;" : "=r"(p) : "r"(nword >> (4 * j)));
                asm("sub.rn.f16x2 %0, %0, %1;" : "+r"(p) : "r"(nzz));
                asm("mul.rn.f16x2 %0, %1, %2;" : "=r"(r[j]) : "r"(p), "r"(ns2));
            }
            asm volatile("st.shared.v4.b32 [%0], {%1,%2,%3,%4};"
                :: "r"(dq_sts + nwoff), "r"(r[0]), "r"(r[1]), "r"(r[2]), "r"(r[3]) : "memory");
            asm volatile("cp.async.wait_group 0;" ::: "memory");
        }
        __syncthreads();
    }

    // ================= epilogue =================
    {
        const int r  = lane >> 2;
        const int gn0 = nblk + nw0 + (lane & 3) * 2;
#pragma unroll
        for (int t = 0; t < 2; t++) {
            const int gn = gn0 + t * 8;
            const float b0 = bias[gn], b1 = bias[gn + 1];
            float2 v0 = make_float2(acc[t][0] + b0, acc[t][1] + b1);
            float2 v1 = make_float2(acc[t][2] + b0, acc[t][3] + b1);
            *reinterpret_cast<float2*>(out + (size_t)(m0 + r)     * N_DIM + gn) = v0;
            *reinterpret_cast<float2*>(out + (size_t)(m0 + r + 8) * N_DIM + gn) = v1;
        }
    }
}

// ---------------------------------------------------------------------------
extern "C" void kernel_launch(void* const* d_in, const int* in_sizes, int n_in,
                              void* d_out, int out_size) {
    const float* x       = (const float*)d_in[0];
    const int*   qweight = (const int*)  d_in[1];
    const int*   qzeros  = (const int*)  d_in[2];
    const float* scales  = (const float*)d_in[3];
    const float* bias    = (const float*)d_in[4];
    float*       out     = (float*)d_out;

    prep_x_kernel<<<128, 256>>>(x);
    gptq_hmma_kernel<<<N_DIM / NTILE, NTHREADS>>>(qweight, qzeros, scales, bias, out);
}

// round 8
// speedup vs baseline: 4.6416x; 1.1715x over previous
#include <cuda_runtime.h>
#include <cuda_fp16.h>
#include <cstdint>

#define M_DIM    64
#define K_DIM    4096
#define N_DIM    11008
#define NGROUPS  32
#define KC       64                    // k per chunk
#define NCHUNKS  (K_DIM / KC)          // 64
#define NTILE    32                    // n columns per CTA
#define NTHREADS 128

// One-time fp16 image of x with k-permutation baked in:
// within each 8-k word, slot p holds original nibble index jmap[p],
// jmap = {0,4,1,5,2,6,3,7}  (matches the LOP3 pair extraction (j, j+4)).
__device__ __half g_xh[M_DIM * K_DIM];   // 512 KB

__device__ __forceinline__ uint32_t smem_u32(const void* p) {
    uint32_t a;
    asm("{ .reg .u64 t; cvta.to.shared.u64 t, %1; cvt.u32.u64 %0, t; }" : "=r"(a) : "l"(p));
    return a;
}

// ---------------------------------------------------------------------------
// Kernel 1: x[M,K] fp32 -> g_xh fp16 with permuted k-order within 8-k words
// ---------------------------------------------------------------------------
__global__ __launch_bounds__(256) void prep_x_kernel(const float* __restrict__ x) {
    const int t = blockIdx.x * 256 + threadIdx.x;   // 32768 threads
    const int i = t & 511;                          // k-word (8 k each)
    const int m = t >> 9;                           // 0..63
    const float* src = x + m * K_DIM + 8 * i;
    __half2 h[4];
    h[0] = __floats2half2_rn(src[0], src[4]);
    h[1] = __floats2half2_rn(src[1], src[5]);
    h[2] = __floats2half2_rn(src[2], src[6]);
    h[3] = __floats2half2_rn(src[3], src[7]);
    *reinterpret_cast<uint4*>(g_xh + m * K_DIM + 8 * i) = *reinterpret_cast<const uint4*>(h);
}

// ---------------------------------------------------------------------------
// Kernel 2: fused int4-dequant GEMM via mma.sync m16n8k16 (fp16 in, fp32 acc)
// CTA: 64m x 32n, 4 warps (2m x 2n), warp tile 32m x 16n, K chunked at 64.
// SMEM swizzle: 16B group kg at row r lives at  r*128 + ((kg ^ (r&7))*16).
// ---------------------------------------------------------------------------
__device__ __forceinline__ void dequant_word(unsigned word, uint32_t zz, uint32_t s2,
                                             uint32_t sts) {
    uint32_t r[4];
#pragma unroll
    for (int j = 0; j < 4; j++) {
        uint32_t p;
        asm("lop3.b32 %0, %1, 0x000F000F, 0x64006400, 0xEA;" : "=r"(p) : "r"(word >> (4 * j)));
        asm("sub.rn.f16x2 %0, %0, %1;" : "+r"(p) : "r"(zz));
        asm("mul.rn.f16x2 %0, %1, %2;" : "=r"(r[j]) : "r"(p), "r"(s2));
    }
    asm volatile("st.shared.v4.b32 [%0], {%1,%2,%3,%4};"
        :: "r"(sts), "r"(r[0]), "r"(r[1]), "r"(r[2]), "r"(r[3]) : "memory");
}

__global__ __launch_bounds__(NTHREADS, 6)
void gptq_hmma_kernel(const int*   __restrict__ qweight,  // [K/8, N]
                      const int*   __restrict__ qzeros,   // [NGROUPS, N/8]
                      const float* __restrict__ scales,   // [NGROUPS, N]
                      const float* __restrict__ bias,     // [N]
                      float*       __restrict__ out)      // [M, N]
{
    __shared__ __half a_s[2][M_DIM * KC];   // x tile   2 x 8 KB
    __shared__ __half w_s[2][NTILE * KC];   // W tile   2 x 4 KB

    const int tid  = threadIdx.x;
    const int lane = tid & 31;
    const int wid  = tid >> 5;
    const int nblk = blockIdx.x * NTILE;

    const uint32_t a_base = smem_u32(a_s);
    const uint32_t w_base = smem_u32(w_s);

    // ---- dequant assignment: two qweight words / thread / chunk (same column)
    const int dq_n   = tid & 31;            // local n
    const int dq_kw0 = tid >> 5;            // 0..3
    const int dq_kw1 = dq_kw0 + 4;          // 4..7
    const int dq_gn  = nblk + dq_n;
    const uint32_t dq_sts0 = w_base + (uint32_t)(dq_n * 128 + ((dq_kw0 ^ (dq_n & 7)) * 16));
    const uint32_t dq_sts1 = w_base + (uint32_t)(dq_n * 128 + ((dq_kw1 ^ (dq_n & 7)) * 16));

    // ---- x stage assignment: four 16B groups / thread / chunk
    uint32_t xs_dst[4];
    const __half* xs_src[4];
#pragma unroll
    for (int i = 0; i < 4; i++) {
        const int v  = tid + i * NTHREADS;   // 0..511
        const int m  = v >> 3;
        const int kg = v & 7;
        xs_dst[i] = a_base + (uint32_t)(m * 128 + ((kg ^ (m & 7)) * 16));
        xs_src[i] = g_xh + m * K_DIM + kg * 8;
    }

    // ---- compute assignment: warp (wm, wn), tile 32m x 16n
    const int wm = wid & 1, wn = wid >> 1;
    const int m0  = wm * 32;
    const int nw0 = wn * 16;
    const int lrow_a = m0  + (lane & 15);    // A subtile 0 rows
    const int lrow_b = nw0 + (lane & 15);
    const int khalf  = lane >> 4;            // 0: k+0, 1: k+8
    const uint32_t ldm_a0 = a_base + (uint32_t)(lrow_a * 128);
    const uint32_t ldm_a1 = ldm_a0 + 16u * 128u;     // rows +16 (same swizzle: (r+16)&7==r&7)
    const uint32_t ldm_b  = w_base + (uint32_t)(lrow_b * 128);
    const int swz_a = lrow_a & 7, swz_b = lrow_b & 7;

    float acc[2][2][4] = {};   // [m-subtile][n8-tile][4]

    // ================= stage chunk 0 =================
    {
#pragma unroll
        for (int i = 0; i < 4; i++)
            asm volatile("cp.async.ca.shared.global [%0], [%1], 16;"
                :: "r"(xs_dst[i]), "l"(xs_src[i]) : "memory");
        asm volatile("cp.async.commit_group;" ::: "memory");

        const unsigned w0 = (unsigned)qweight[dq_kw0 * N_DIM + dq_gn];
        const unsigned w1 = (unsigned)qweight[dq_kw1 * N_DIM + dq_gn];
        const float    s  = scales[dq_gn];
        const int      zw = qzeros[dq_gn >> 3];
        const int      z  = ((zw >> ((dq_gn & 7) * 4)) & 15) + 1;
        const uint32_t zz = 0x64006400u + (uint32_t)z * 0x00010001u;
        const uint16_t hb = __half_as_ushort(__float2half_rn(s));
        const uint32_t s2 = ((uint32_t)hb << 16) | hb;
        dequant_word(w0, zz, s2, dq_sts0);
        dequant_word(w1, zz, s2, dq_sts1);
        asm volatile("cp.async.wait_group 0;" ::: "memory");
    }
    __syncthreads();

    // ================= main loop =================
#pragma unroll 1
    for (int c = 0; c < NCHUNKS; c++) {
        const uint32_t aoff  = (uint32_t)((c & 1) * (M_DIM * KC * 2));
        const uint32_t woff  = (uint32_t)((c & 1) * (NTILE * KC * 2));
        const uint32_t naoff = (uint32_t)(((c + 1) & 1) * (M_DIM * KC * 2));
        const uint32_t nwoff = (uint32_t)(((c + 1) & 1) * (NTILE * KC * 2));

        unsigned nw0d = 0, nw1d = 0; uint32_t nzz = 0, ns2 = 0;
        const bool has_next = (c + 1 < NCHUNKS);
        if (has_next) {
            const int nc = c + 1;
#pragma unroll
            for (int i = 0; i < 4; i++)
                asm volatile("cp.async.ca.shared.global [%0], [%1], 16;"
                    :: "r"(xs_dst[i] + naoff), "l"(xs_src[i] + nc * KC) : "memory");
            asm volatile("cp.async.commit_group;" ::: "memory");

            const int g = nc >> 1;
            nw0d = (unsigned)qweight[(nc * 8 + dq_kw0) * N_DIM + dq_gn];
            nw1d = (unsigned)qweight[(nc * 8 + dq_kw1) * N_DIM + dq_gn];
            const float s  = scales[g * N_DIM + dq_gn];
            const int   zw = qzeros[g * (N_DIM / 8) + (dq_gn >> 3)];
            const int   z  = ((zw >> ((dq_gn & 7) * 4)) & 15) + 1;
            nzz = 0x64006400u + (uint32_t)z * 0x00010001u;
            const uint16_t hb = __half_as_ushort(__float2half_rn(s));
            ns2 = ((uint32_t)hb << 16) | hb;
        }

        // ---- compute chunk c: 4 k-tiles of 16, 4 MMAs each (4 indep chains)
#pragma unroll
        for (int kt = 0; kt < 4; kt++) {
            const int kg = 2 * kt + khalf;
            uint32_t a0[4], a1[4], b[4];
            asm volatile("ldmatrix.sync.aligned.m8n8.x4.shared.b16 {%0,%1,%2,%3}, [%4];"
                : "=r"(a0[0]), "=r"(a0[1]), "=r"(a0[2]), "=r"(a0[3])
                : "r"(ldm_a0 + aoff + (uint32_t)((kg ^ swz_a) * 16)));
            asm volatile("ldmatrix.sync.aligned.m8n8.x4.shared.b16 {%0,%1,%2,%3}, [%4];"
                : "=r"(a1[0]), "=r"(a1[1]), "=r"(a1[2]), "=r"(a1[3])
                : "r"(ldm_a1 + aoff + (uint32_t)((kg ^ swz_a) * 16)));
            asm volatile("ldmatrix.sync.aligned.m8n8.x4.shared.b16 {%0,%1,%2,%3}, [%4];"
                : "=r"(b[0]), "=r"(b[1]), "=r"(b[2]), "=r"(b[3])
                : "r"(ldm_b + woff + (uint32_t)((kg ^ swz_b) * 16)));
#pragma unroll
            for (int mi = 0; mi < 2; mi++) {
                const uint32_t* a = mi ? a1 : a0;
                asm volatile(
                    "mma.sync.aligned.m16n8k16.row.col.f32.f16.f16.f32 "
                    "{%0,%1,%2,%3}, {%4,%5,%6,%7}, {%8,%9}, {%0,%1,%2,%3};"
                    : "+f"(acc[mi][0][0]), "+f"(acc[mi][0][1]), "+f"(acc[mi][0][2]), "+f"(acc[mi][0][3])
                    : "r"(a[0]), "r"(a[1]), "r"(a[2]), "r"(a[3]), "r"(b[0]), "r"(b[2]));
                asm volatile(
                    "mma.sync.aligned.m16n8k16.row.col.f32.f16.f16.f32 "
                    "{%0,%1,%2,%3}, {%4,%5,%6,%7}, {%8,%9}, {%0,%1,%2,%3};"
                    : "+f"(acc[mi][1][0]), "+f"(acc[mi][1][1]), "+f"(acc[mi][1][2]), "+f"(acc[mi][1][3])
                    : "r"(a[0]), "r"(a[1]), "r"(a[2]), "r"(a[3]), "r"(b[1]), "r"(b[3]));
            }
        }

        if (has_next) {
            dequant_word(nw0d, nzz, ns2, dq_sts0 + nwoff);
            dequant_word(nw1d, nzz, ns2, dq_sts1 + nwoff);
            asm volatile("cp.async.wait_group 0;" ::: "memory");
        }
        __syncthreads();
    }

    // ================= epilogue =================
    {
        const int r   = lane >> 2;
        const int gn0 = nblk + nw0 + (lane & 3) * 2;
#pragma unroll
        for (int mi = 0; mi < 2; mi++) {
            const int mrow = m0 + mi * 16;
#pragma unroll
            for (int t = 0; t < 2; t++) {
                const int gn = gn0 + t * 8;
                const float b0 = bias[gn], b1 = bias[gn + 1];
                float2 v0 = make_float2(acc[mi][t][0] + b0, acc[mi][t][1] + b1);
                float2 v1 = make_float2(acc[mi][t][2] + b0, acc[mi][t][3] + b1);
                *reinterpret_cast<float2*>(out + (size_t)(mrow + r)     * N_DIM + gn) = v0;
                *reinterpret_cast<float2*>(out + (size_t)(mrow + r + 8) * N_DIM + gn) = v1;
            }
        }
    }
}

// ---------------------------------------------------------------------------
extern "C" void kernel_launch(void* const* d_in, const int* in_sizes, int n_in,
                              void* d_out, int out_size) {
    const float* x       = (const float*)d_in[0];
    const int*   qweight = (const int*)  d_in[1];
    const int*   qzeros  = (const int*)  d_in[2];
    const float* scales  = (const float*)d_in[3];
    const float* bias    = (const float*)d_in[4];
    float*       out     = (float*)d_out;

    prep_x_kernel<<<128, 256>>>(x);
    gptq_hmma_kernel<<<N_DIM / NTILE, NTHREADS>>>(qweight, qzeros, scales, bias, out);
}